// round 1
// baseline (speedup 1.0000x reference)
#include <cuda_runtime.h>
#include <math.h>

#define Bc 2
#define Sc 2048
#define Dc 1024
#define Hc 16
#define DPc 64

static const size_t SZ_QKV  = (size_t)Bc * Sc * Dc;        // 4194304
static const size_t SZ_ATTN = (size_t)Bc * Hc * Sc * Sc;   // 134217728

// Scratch (allocation-free: __device__ globals)
__device__ float g_ctx[(size_t)Bc * Sc * Dc];
__device__ float g_mbuf[(size_t)Bc * Hc * Sc];
__device__ float g_lbuf[(size_t)Bc * Hc * Sc];

// ---------------------------------------------------------------------------
// GEMM: C[M,N] = X[M,K] @ W[N,K]^T + bias   (torch Linear semantics)
// 128x128 block tile, BK=16, 256 threads, 8x8 per-thread microtile.
// ---------------------------------------------------------------------------
__global__ __launch_bounds__(256, 1)
void gemm_bias_kernel(const float* __restrict__ X, const float* __restrict__ W,
                      const float* __restrict__ bias, float* __restrict__ C,
                      int M, int N, int K)
{
    __shared__ float As[16][132];
    __shared__ float Bs[16][132];
    const int tid = threadIdx.x;
    const int m0 = blockIdx.y * 128;
    const int n0 = blockIdx.x * 128;
    const int tm = (tid >> 4) * 8;
    const int tn = (tid & 15) * 8;

    float acc[8][8];
#pragma unroll
    for (int i = 0; i < 8; i++)
#pragma unroll
        for (int j = 0; j < 8; j++) acc[i][j] = 0.0f;

    for (int k0 = 0; k0 < K; k0 += 16) {
#pragma unroll
        for (int i = 0; i < 2; i++) {
            int id  = tid + i * 256;        // 0..511
            int row = id >> 2;              // 0..127
            int c4  = (id & 3) << 2;        // 0,4,8,12
            float4 va = *(const float4*)(X + (size_t)(m0 + row) * K + k0 + c4);
            As[c4 + 0][row] = va.x; As[c4 + 1][row] = va.y;
            As[c4 + 2][row] = va.z; As[c4 + 3][row] = va.w;
            float4 vb = *(const float4*)(W + (size_t)(n0 + row) * K + k0 + c4);
            Bs[c4 + 0][row] = vb.x; Bs[c4 + 1][row] = vb.y;
            Bs[c4 + 2][row] = vb.z; Bs[c4 + 3][row] = vb.w;
        }
        __syncthreads();
#pragma unroll
        for (int kk = 0; kk < 16; kk++) {
            float a[8], b[8];
            *(float4*)&a[0] = *(const float4*)&As[kk][tm];
            *(float4*)&a[4] = *(const float4*)&As[kk][tm + 4];
            *(float4*)&b[0] = *(const float4*)&Bs[kk][tn];
            *(float4*)&b[4] = *(const float4*)&Bs[kk][tn + 4];
#pragma unroll
            for (int i = 0; i < 8; i++)
#pragma unroll
                for (int j = 0; j < 8; j++)
                    acc[i][j] = fmaf(a[i], b[j], acc[i][j]);
        }
        __syncthreads();
    }

    float bv[8];
#pragma unroll
    for (int j = 0; j < 8; j++) bv[j] = __ldg(&bias[n0 + tn + j]);
#pragma unroll
    for (int i = 0; i < 8; i++) {
        size_t off = (size_t)(m0 + tm + i) * N + n0 + tn;
        float4 o0 = make_float4(acc[i][0] + bv[0], acc[i][1] + bv[1],
                                acc[i][2] + bv[2], acc[i][3] + bv[3]);
        float4 o1 = make_float4(acc[i][4] + bv[4], acc[i][5] + bv[5],
                                acc[i][6] + bv[6], acc[i][7] + bv[7]);
        *(float4*)(C + off)     = o0;
        *(float4*)(C + off + 4) = o1;
    }
}

// ---------------------------------------------------------------------------
// Attention pass 1: per (b,h,64-row tile), compute exact row max m and
// sum-exp l over the causal row (online accumulation over 64-col K tiles).
// ---------------------------------------------------------------------------
__global__ __launch_bounds__(256, 1)
void attn_stats_kernel(const float* __restrict__ q, const float* __restrict__ k)
{
    __shared__ float Qt[64][68];   // [depth][row]
    __shared__ float Kt[64][68];   // [depth][col]
    const int b = blockIdx.z, h = blockIdx.y, it = blockIdx.x;
    const int r0 = it * 64;
    const int tid = threadIdx.x;
    const int ty = tid >> 4, tx = tid & 15;
    const float* qp = q + ((size_t)b * Sc + r0) * Dc + h * DPc;
    const float* kp = k + (size_t)b * Sc * Dc + h * DPc;

#pragma unroll
    for (int i = 0; i < 4; i++) {
        int id  = tid + i * 256;
        int row = id >> 4;
        int c4  = (id & 15) << 2;
        float4 va = *(const float4*)(qp + (size_t)row * Dc + c4);
        Qt[c4 + 0][row] = va.x; Qt[c4 + 1][row] = va.y;
        Qt[c4 + 2][row] = va.z; Qt[c4 + 3][row] = va.w;
    }

    float m[4], l[4];
#pragma unroll
    for (int ii = 0; ii < 4; ii++) { m[ii] = -INFINITY; l[ii] = 0.0f; }

    for (int jt = 0; jt <= it; jt++) {
        const int j0 = jt * 64;
        __syncthreads();
#pragma unroll
        for (int i = 0; i < 4; i++) {
            int id  = tid + i * 256;
            int row = id >> 4;
            int c4  = (id & 15) << 2;
            float4 vk = *(const float4*)(kp + (size_t)(j0 + row) * Dc + c4);
            Kt[c4 + 0][row] = vk.x; Kt[c4 + 1][row] = vk.y;
            Kt[c4 + 2][row] = vk.z; Kt[c4 + 3][row] = vk.w;
        }
        __syncthreads();

        float acc[4][4] = {};
#pragma unroll 8
        for (int kk = 0; kk < 64; kk++) {
            float4 qf = *(const float4*)&Qt[kk][ty * 4];
            float4 kf = *(const float4*)&Kt[kk][tx * 4];
            float qv[4] = {qf.x, qf.y, qf.z, qf.w};
            float kv[4] = {kf.x, kf.y, kf.z, kf.w};
#pragma unroll
            for (int ii = 0; ii < 4; ii++)
#pragma unroll
                for (int jj = 0; jj < 4; jj++)
                    acc[ii][jj] = fmaf(qv[ii], kv[jj], acc[ii][jj]);
        }

        float s[4][4];
        const bool diag = (jt == it);
#pragma unroll
        for (int ii = 0; ii < 4; ii++)
#pragma unroll
            for (int jj = 0; jj < 4; jj++) {
                float val = acc[ii][jj] * 0.125f;
                if (diag && (tx * 4 + jj) > (ty * 4 + ii)) val = -INFINITY;
                s[ii][jj] = val;
            }

#pragma unroll
        for (int ii = 0; ii < 4; ii++) {
            float tmax = fmaxf(fmaxf(s[ii][0], s[ii][1]), fmaxf(s[ii][2], s[ii][3]));
#pragma unroll
            for (int off = 8; off >= 1; off >>= 1)
                tmax = fmaxf(tmax, __shfl_xor_sync(0xffffffffu, tmax, off, 16));
            float mn = fmaxf(m[ii], tmax);
            float ssum = __expf(s[ii][0] - mn) + __expf(s[ii][1] - mn) +
                         __expf(s[ii][2] - mn) + __expf(s[ii][3] - mn);
#pragma unroll
            for (int off = 8; off >= 1; off >>= 1)
                ssum += __shfl_xor_sync(0xffffffffu, ssum, off, 16);
            l[ii] = l[ii] * __expf(m[ii] - mn) + ssum;
            m[ii] = mn;
        }
    }

    if (tx == 0) {
#pragma unroll
        for (int ii = 0; ii < 4; ii++) {
            size_t ridx = ((size_t)(b * Hc + h)) * Sc + r0 + ty * 4 + ii;
            g_mbuf[ridx] = m[ii];
            g_lbuf[ridx] = l[ii];
        }
    }
}

// ---------------------------------------------------------------------------
// Attention pass 2: recompute logits, store normalized attn (once), zero-fill
// causal upper triangle, and fuse P@V into g_ctx.
// Dynamic smem: Qt, Kt, Vs, Ps each [64][68] floats = 69632 B.
// ---------------------------------------------------------------------------
__global__ __launch_bounds__(256, 1)
void attn_pv_kernel(const float* __restrict__ q, const float* __restrict__ k,
                    const float* __restrict__ v, float* __restrict__ attn)
{
    extern __shared__ float smraw[];
    float (*Qt)[68] = (float(*)[68])(smraw);
    float (*Kt)[68] = (float(*)[68])(smraw + 64 * 68);
    float (*Vs)[68] = (float(*)[68])(smraw + 2 * 64 * 68);
    float (*Ps)[68] = (float(*)[68])(smraw + 3 * 64 * 68);

    const int b = blockIdx.z, h = blockIdx.y, it = blockIdx.x;
    const int r0 = it * 64;
    const int tid = threadIdx.x;
    const int ty = tid >> 4, tx = tid & 15;
    const float* qp = q + ((size_t)b * Sc + r0) * Dc + h * DPc;
    const float* kp = k + (size_t)b * Sc * Dc + h * DPc;
    const float* vp = v + (size_t)b * Sc * Dc + h * DPc;
    const size_t bh = (size_t)(b * Hc + h);
    float* attnp = attn + bh * Sc * Sc;

#pragma unroll
    for (int i = 0; i < 4; i++) {
        int id  = tid + i * 256;
        int row = id >> 4;
        int c4  = (id & 15) << 2;
        float4 va = *(const float4*)(qp + (size_t)row * Dc + c4);
        Qt[c4 + 0][row] = va.x; Qt[c4 + 1][row] = va.y;
        Qt[c4 + 2][row] = va.z; Qt[c4 + 3][row] = va.w;
    }

    float mrow[4], invl[4];
#pragma unroll
    for (int ii = 0; ii < 4; ii++) {
        size_t ridx = bh * Sc + r0 + ty * 4 + ii;
        mrow[ii] = g_mbuf[ridx];
        invl[ii] = 1.0f / g_lbuf[ridx];
    }

    float cacc[4][4] = {};

    for (int jt = 0; jt <= it; jt++) {
        const int j0 = jt * 64;
        __syncthreads();
#pragma unroll
        for (int i = 0; i < 4; i++) {
            int id  = tid + i * 256;
            int row = id >> 4;
            int c4  = (id & 15) << 2;
            float4 vk = *(const float4*)(kp + (size_t)(j0 + row) * Dc + c4);
            Kt[c4 + 0][row] = vk.x; Kt[c4 + 1][row] = vk.y;
            Kt[c4 + 2][row] = vk.z; Kt[c4 + 3][row] = vk.w;
            float4 vv = *(const float4*)(vp + (size_t)(j0 + row) * Dc + c4);
            *(float4*)&Vs[row][c4] = vv;
        }
        __syncthreads();

        float acc[4][4] = {};
#pragma unroll 8
        for (int kk = 0; kk < 64; kk++) {
            float4 qf = *(const float4*)&Qt[kk][ty * 4];
            float4 kf = *(const float4*)&Kt[kk][tx * 4];
            float qv[4] = {qf.x, qf.y, qf.z, qf.w};
            float kv[4] = {kf.x, kf.y, kf.z, kf.w};
#pragma unroll
            for (int ii = 0; ii < 4; ii++)
#pragma unroll
                for (int jj = 0; jj < 4; jj++)
                    acc[ii][jj] = fmaf(qv[ii], kv[jj], acc[ii][jj]);
        }

        const bool diag = (jt == it);
        float p[4][4];
#pragma unroll
        for (int ii = 0; ii < 4; ii++)
#pragma unroll
            for (int jj = 0; jj < 4; jj++) {
                float val;
                if (diag && (tx * 4 + jj) > (ty * 4 + ii)) {
                    val = 0.0f;
                } else {
                    val = __expf(acc[ii][jj] * 0.125f - mrow[ii]) * invl[ii];
                }
                p[ii][jj] = val;
            }

        // store normalized attn tile + stage P for the PV product
#pragma unroll
        for (int ii = 0; ii < 4; ii++) {
            int gi = r0 + ty * 4 + ii;
            float4 pr = make_float4(p[ii][0], p[ii][1], p[ii][2], p[ii][3]);
            *(float4*)&attnp[(size_t)gi * Sc + j0 + tx * 4] = pr;
            *(float4*)&Ps[ty * 4 + ii][tx * 4] = pr;
        }
        __syncthreads();

        // cacc[i][d] += sum_j P[i][j] * V[j][d]
#pragma unroll 4
        for (int jj = 0; jj < 64; jj++) {
            float4 vf = *(const float4*)&Vs[jj][tx * 4];
#pragma unroll
            for (int ii = 0; ii < 4; ii++) {
                float pf = Ps[ty * 4 + ii][jj];
                cacc[ii][0] = fmaf(pf, vf.x, cacc[ii][0]);
                cacc[ii][1] = fmaf(pf, vf.y, cacc[ii][1]);
                cacc[ii][2] = fmaf(pf, vf.z, cacc[ii][2]);
                cacc[ii][3] = fmaf(pf, vf.w, cacc[ii][3]);
            }
        }
    }

    // zero-fill the causal upper triangle (d_out is poisoned; ref has exact 0)
    const int zc0 = (it + 1) * 64;
    for (int r = 0; r < 64; r++) {
        size_t rowoff = (size_t)(r0 + r) * Sc;
        for (int c = zc0 + tid * 4; c < Sc; c += 1024)
            *(float4*)&attnp[rowoff + c] = make_float4(0.f, 0.f, 0.f, 0.f);
    }

    // write ctx in [B,S,D] layout (head h occupies cols h*64..h*64+63)
#pragma unroll
    for (int ii = 0; ii < 4; ii++) {
        int gi = r0 + ty * 4 + ii;
        *(float4*)&g_ctx[((size_t)b * Sc + gi) * Dc + h * DPc + tx * 4] =
            make_float4(cacc[ii][0], cacc[ii][1], cacc[ii][2], cacc[ii][3]);
    }
}

// ---------------------------------------------------------------------------
extern "C" void kernel_launch(void* const* d_in, const int* in_sizes, int n_in,
                              void* d_out, int out_size)
{
    (void)in_sizes; (void)n_in; (void)out_size;
    const float* Q   = (const float*)d_in[0];
    const float* Kin = (const float*)d_in[1];
    const float* Vin = (const float*)d_in[2];
    // d_in[3] = mask (pure causal; applied analytically)
    const float* Wq = (const float*)d_in[4];
    const float* bq = (const float*)d_in[5];
    const float* Wk = (const float*)d_in[6];
    const float* bk = (const float*)d_in[7];
    const float* Wv = (const float*)d_in[8];
    const float* bv = (const float*)d_in[9];
    const float* Wo = (const float*)d_in[10];
    const float* bo = (const float*)d_in[11];

    float* out  = (float*)d_out;
    float* attn = out + SZ_QKV;
    float* qo   = attn + SZ_ATTN;
    float* ko   = qo + SZ_QKV;
    float* vo   = ko + SZ_QKV;

    void* ctxp = nullptr;
    cudaGetSymbolAddress(&ctxp, g_ctx);

    dim3 ggrid(Dc / 128, (Bc * Sc) / 128);
    gemm_bias_kernel<<<ggrid, 256>>>(Q,   Wq, bq, qo, Bc * Sc, Dc, Dc);
    gemm_bias_kernel<<<ggrid, 256>>>(Kin, Wk, bk, ko, Bc * Sc, Dc, Dc);
    gemm_bias_kernel<<<ggrid, 256>>>(Vin, Wv, bv, vo, Bc * Sc, Dc, Dc);

    dim3 agrid(Sc / 64, Hc, Bc);
    attn_stats_kernel<<<agrid, 256>>>(qo, ko);

    const int pv_smem = 4 * 64 * 68 * (int)sizeof(float);
    cudaFuncSetAttribute(attn_pv_kernel,
                         cudaFuncAttributeMaxDynamicSharedMemorySize, pv_smem);
    attn_pv_kernel<<<agrid, 256, pv_smem>>>(qo, ko, vo, attn);

    gemm_bias_kernel<<<ggrid, 256>>>((const float*)ctxp, Wo, bo, out,
                                     Bc * Sc, Dc, Dc);
}

// round 3
// speedup vs baseline: 1.2936x; 1.2936x over previous
#include <cuda_runtime.h>
#include <cuda_bf16.h>
#include <math.h>
#include <stdint.h>

#define Bc 2
#define Sc 2048
#define Dc 1024
#define Hc 16
#define DPc 64

static const size_t SZ_QKV  = (size_t)Bc * Sc * Dc;        // 4194304
static const size_t SZ_ATTN = (size_t)Bc * Hc * Sc * Sc;   // 134217728

// Scratch (allocation-free: __device__ globals)
__device__ float g_ctx[(size_t)Bc * Sc * Dc];
__device__ float g_mbuf[(size_t)Bc * Hc * Sc];
__device__ float g_lbuf[(size_t)Bc * Hc * Sc];

// ---------------------------------------------------------------------------
// helpers
// ---------------------------------------------------------------------------
__device__ __forceinline__ uint32_t smem_u32(const void* p) {
    uint32_t a;
    asm("{ .reg .u64 t; cvta.to.shared.u64 t, %1; cvt.u32.u64 %0, t; }"
        : "=r"(a) : "l"(p));
    return a;
}

__device__ __forceinline__ void mma16816(float* d, const uint32_t* a, const uint32_t* b) {
    asm volatile(
        "mma.sync.aligned.m16n8k16.row.col.f32.bf16.bf16.f32 "
        "{%0,%1,%2,%3}, {%4,%5,%6,%7}, {%8,%9}, {%0,%1,%2,%3};"
        : "+f"(d[0]), "+f"(d[1]), "+f"(d[2]), "+f"(d[3])
        : "r"(a[0]), "r"(a[1]), "r"(a[2]), "r"(a[3]), "r"(b[0]), "r"(b[1]));
}
__device__ __forceinline__ void ldsm4(uint32_t* r, uint32_t addr) {
    asm volatile("ldmatrix.sync.aligned.m8n8.x4.shared.b16 {%0,%1,%2,%3}, [%4];"
                 : "=r"(r[0]), "=r"(r[1]), "=r"(r[2]), "=r"(r[3]) : "r"(addr));
}

__device__ __forceinline__ uint32_t pack_hi(float x, float y) {
    __nv_bfloat162 h = __float22bfloat162_rn(make_float2(x, y));
    return *(uint32_t*)&h;
}
__device__ __forceinline__ uint32_t pack_lo(float x, float y) {
    __nv_bfloat16 hx = __float2bfloat16(x), hy = __float2bfloat16(y);
    __nv_bfloat162 l = __float22bfloat162_rn(
        make_float2(x - __bfloat162float(hx), y - __bfloat162float(hy)));
    return *(uint32_t*)&l;
}

// ---------------------------------------------------------------------------
// Tensor-core GEMM: C[M,N] = A[M,K] @ B[N,K]^T + bias  (f32 in/out)
// bf16 hi/lo split (3 mma terms). 128x128x32 CTA tile, 8 warps, 64x32 warp tile.
// SMEM planes: [128 rows][40 bf16] (80B rows, ldmatrix conflict-free),
// double-buffered: {Ahi,Alo,Bhi,Blo} x 2 = 81920 B dynamic smem.
// ---------------------------------------------------------------------------
#define ROWB 40
#define PLANE (128 * ROWB * 2)   // bytes per plane = 10240

__global__ __launch_bounds__(256, 1)
void gemm_mma_kernel(const float* __restrict__ A, const float* __restrict__ B,
                     const float* __restrict__ bias, float* __restrict__ C,
                     int M, int N, int K)
{
    extern __shared__ __align__(128) char sm[];
    const uint32_t smb = smem_u32(sm);
    const int tid = threadIdx.x;
    const int wid = tid >> 5, lane = tid & 31;
    const int m0 = blockIdx.y * 128, n0 = blockIdx.x * 128;
    const int warp_m = (wid & 1) * 64;     // 2 warps over M
    const int warp_n = (wid >> 1) * 32;    // 4 warps over N

    // plane base byte offsets: buf*4 planes + {Ahi=0, Alo=1, Bhi=2, Blo=3}
    auto plane = [&](int buf, int p) -> uint32_t { return (uint32_t)((buf * 4 + p) * PLANE); };

    float acc[4][4][4];
#pragma unroll
    for (int i = 0; i < 4; i++)
#pragma unroll
        for (int j = 0; j < 4; j++)
#pragma unroll
            for (int c = 0; c < 4; c++) acc[i][j][c] = 0.0f;

    const int nch = K / 32;
    float4 ra[4], rb[4];

    // ld-gen: each thread loads 4 float4 from A tile and 4 from B tile
    auto load_regs = [&](int ch) {
        const size_t gk = (size_t)ch * 32;
#pragma unroll
        for (int e = 0; e < 4; e++) {
            int id = tid + e * 256;       // 0..1023
            int row = id >> 3;            // 0..127
            int c4 = (id & 7) << 2;       // 0..28
            ra[e] = *(const float4*)(A + (size_t)(m0 + row) * K + gk + c4);
            rb[e] = *(const float4*)(B + (size_t)(n0 + row) * K + gk + c4);
        }
    };
    auto sts_regs = [&](int buf) {
#pragma unroll
        for (int e = 0; e < 4; e++) {
            int id = tid + e * 256;
            int row = id >> 3;
            int c4 = (id & 7) << 2;
            uint32_t off = (uint32_t)(row * 80 + c4 * 2);
            uint2 h, l;
            h.x = pack_hi(ra[e].x, ra[e].y); h.y = pack_hi(ra[e].z, ra[e].w);
            l.x = pack_lo(ra[e].x, ra[e].y); l.y = pack_lo(ra[e].z, ra[e].w);
            *(uint2*)(sm + plane(buf, 0) + off) = h;
            *(uint2*)(sm + plane(buf, 1) + off) = l;
            h.x = pack_hi(rb[e].x, rb[e].y); h.y = pack_hi(rb[e].z, rb[e].w);
            l.x = pack_lo(rb[e].x, rb[e].y); l.y = pack_lo(rb[e].z, rb[e].w);
            *(uint2*)(sm + plane(buf, 2) + off) = h;
            *(uint2*)(sm + plane(buf, 3) + off) = l;
        }
    };

    load_regs(0);
    sts_regs(0);
    __syncthreads();

    for (int ch = 0; ch < nch; ch++) {
        const int buf = ch & 1;
        if (ch + 1 < nch) load_regs(ch + 1);

        // A ldmatrix address components
        const int arow = lane & 15;          // row within m16
        const int acol = (lane >> 4) * 8;    // k sub-block
        // B ldmatrix: lanes 0..31 -> 4 8x8 matrices (n16 x k16)
        const int bg = lane >> 3, bw = lane & 7;

#pragma unroll
        for (int ks = 0; ks < 2; ks++) {
            const int k16 = ks * 16;
            uint32_t ah[4][4], al[4][4];
#pragma unroll
            for (int mt = 0; mt < 4; mt++) {
                uint32_t off = (uint32_t)((warp_m + mt * 16 + arow) * 80 + (k16 + acol) * 2);
                ldsm4(ah[mt], smb + plane(buf, 0) + off);
                ldsm4(al[mt], smb + plane(buf, 1) + off);
            }
            uint32_t bh[4][2], bl[4][2];
#pragma unroll
            for (int nb = 0; nb < 2; nb++) {
                uint32_t off = (uint32_t)((warp_n + nb * 16 + (bg & 1) * 8 + bw) * 80
                                          + (k16 + (bg >> 1) * 8) * 2);
                uint32_t t[4];
                ldsm4(t, smb + plane(buf, 2) + off);
                bh[nb * 2 + 0][0] = t[0]; bh[nb * 2 + 0][1] = t[2];
                bh[nb * 2 + 1][0] = t[1]; bh[nb * 2 + 1][1] = t[3];
                ldsm4(t, smb + plane(buf, 3) + off);
                bl[nb * 2 + 0][0] = t[0]; bl[nb * 2 + 0][1] = t[2];
                bl[nb * 2 + 1][0] = t[1]; bl[nb * 2 + 1][1] = t[3];
            }
#pragma unroll
            for (int mt = 0; mt < 4; mt++)
#pragma unroll
                for (int nt = 0; nt < 4; nt++) {
                    mma16816(acc[mt][nt], ah[mt], bh[nt]);
                    mma16816(acc[mt][nt], ah[mt], bl[nt]);
                    mma16816(acc[mt][nt], al[mt], bh[nt]);
                }
        }

        if (ch + 1 < nch) sts_regs((ch + 1) & 1);
        __syncthreads();
    }

    // epilogue: acc -> C with bias
    const int lr = lane >> 2, lc = (lane & 3) * 2;
#pragma unroll
    for (int nt = 0; nt < 4; nt++) {
        int col = n0 + warp_n + nt * 8 + lc;
        float2 bv = *(const float2*)&bias[col];
#pragma unroll
        for (int mt = 0; mt < 4; mt++) {
            int r0 = m0 + warp_m + mt * 16 + lr;
            float2 o0 = make_float2(acc[mt][nt][0] + bv.x, acc[mt][nt][1] + bv.y);
            float2 o1 = make_float2(acc[mt][nt][2] + bv.x, acc[mt][nt][3] + bv.y);
            *(float2*)(C + (size_t)r0 * N + col) = o0;
            *(float2*)(C + (size_t)(r0 + 8) * N + col) = o1;
        }
    }
}

// ---------------------------------------------------------------------------
// Attention pass 1 (unchanged)
// ---------------------------------------------------------------------------
__global__ __launch_bounds__(256, 1)
void attn_stats_kernel(const float* __restrict__ q, const float* __restrict__ k)
{
    __shared__ float Qt[64][68];
    __shared__ float Kt[64][68];
    const int b = blockIdx.z, h = blockIdx.y, it = blockIdx.x;
    const int r0 = it * 64;
    const int tid = threadIdx.x;
    const int ty = tid >> 4, tx = tid & 15;
    const float* qp = q + ((size_t)b * Sc + r0) * Dc + h * DPc;
    const float* kp = k + (size_t)b * Sc * Dc + h * DPc;

#pragma unroll
    for (int i = 0; i < 4; i++) {
        int id = tid + i * 256;
        int row = id >> 4;
        int c4 = (id & 15) << 2;
        float4 va = *(const float4*)(qp + (size_t)row * Dc + c4);
        Qt[c4 + 0][row] = va.x; Qt[c4 + 1][row] = va.y;
        Qt[c4 + 2][row] = va.z; Qt[c4 + 3][row] = va.w;
    }

    float m[4], l[4];
#pragma unroll
    for (int ii = 0; ii < 4; ii++) { m[ii] = -INFINITY; l[ii] = 0.0f; }

    for (int jt = 0; jt <= it; jt++) {
        const int j0 = jt * 64;
        __syncthreads();
#pragma unroll
        for (int i = 0; i < 4; i++) {
            int id = tid + i * 256;
            int row = id >> 4;
            int c4 = (id & 15) << 2;
            float4 vk = *(const float4*)(kp + (size_t)(j0 + row) * Dc + c4);
            Kt[c4 + 0][row] = vk.x; Kt[c4 + 1][row] = vk.y;
            Kt[c4 + 2][row] = vk.z; Kt[c4 + 3][row] = vk.w;
        }
        __syncthreads();

        float acc[4][4] = {};
#pragma unroll 8
        for (int kk = 0; kk < 64; kk++) {
            float4 qf = *(const float4*)&Qt[kk][ty * 4];
            float4 kf = *(const float4*)&Kt[kk][tx * 4];
            float qv[4] = {qf.x, qf.y, qf.z, qf.w};
            float kv[4] = {kf.x, kf.y, kf.z, kf.w};
#pragma unroll
            for (int ii = 0; ii < 4; ii++)
#pragma unroll
                for (int jj = 0; jj < 4; jj++)
                    acc[ii][jj] = fmaf(qv[ii], kv[jj], acc[ii][jj]);
        }

        float s[4][4];
        const bool diag = (jt == it);
#pragma unroll
        for (int ii = 0; ii < 4; ii++)
#pragma unroll
            for (int jj = 0; jj < 4; jj++) {
                float val = acc[ii][jj] * 0.125f;
                if (diag && (tx * 4 + jj) > (ty * 4 + ii)) val = -INFINITY;
                s[ii][jj] = val;
            }

#pragma unroll
        for (int ii = 0; ii < 4; ii++) {
            float tmax = fmaxf(fmaxf(s[ii][0], s[ii][1]), fmaxf(s[ii][2], s[ii][3]));
#pragma unroll
            for (int off = 8; off >= 1; off >>= 1)
                tmax = fmaxf(tmax, __shfl_xor_sync(0xffffffffu, tmax, off, 16));
            float mn = fmaxf(m[ii], tmax);
            float ssum = __expf(s[ii][0] - mn) + __expf(s[ii][1] - mn) +
                         __expf(s[ii][2] - mn) + __expf(s[ii][3] - mn);
#pragma unroll
            for (int off = 8; off >= 1; off >>= 1)
                ssum += __shfl_xor_sync(0xffffffffu, ssum, off, 16);
            l[ii] = l[ii] * __expf(m[ii] - mn) + ssum;
            m[ii] = mn;
        }
    }

    if (tx == 0) {
#pragma unroll
        for (int ii = 0; ii < 4; ii++) {
            size_t ridx = ((size_t)(b * Hc + h)) * Sc + r0 + ty * 4 + ii;
            g_mbuf[ridx] = m[ii];
            g_lbuf[ridx] = l[ii];
        }
    }
}

// ---------------------------------------------------------------------------
// Attention pass 2 (unchanged)
// ---------------------------------------------------------------------------
__global__ __launch_bounds__(256, 1)
void attn_pv_kernel(const float* __restrict__ q, const float* __restrict__ k,
                    const float* __restrict__ v, float* __restrict__ attn)
{
    extern __shared__ float smraw[];
    float (*Qt)[68] = (float(*)[68])(smraw);
    float (*Kt)[68] = (float(*)[68])(smraw + 64 * 68);
    float (*Vs)[68] = (float(*)[68])(smraw + 2 * 64 * 68);
    float (*Ps)[68] = (float(*)[68])(smraw + 3 * 64 * 68);

    const int b = blockIdx.z, h = blockIdx.y, it = blockIdx.x;
    const int r0 = it * 64;
    const int tid = threadIdx.x;
    const int ty = tid >> 4, tx = tid & 15;
    const float* qp = q + ((size_t)b * Sc + r0) * Dc + h * DPc;
    const float* kp = k + (size_t)b * Sc * Dc + h * DPc;
    const float* vp = v + (size_t)b * Sc * Dc + h * DPc;
    const size_t bh = (size_t)(b * Hc + h);
    float* attnp = attn + bh * Sc * Sc;

#pragma unroll
    for (int i = 0; i < 4; i++) {
        int id = tid + i * 256;
        int row = id >> 4;
        int c4 = (id & 15) << 2;
        float4 va = *(const float4*)(qp + (size_t)row * Dc + c4);
        Qt[c4 + 0][row] = va.x; Qt[c4 + 1][row] = va.y;
        Qt[c4 + 2][row] = va.z; Qt[c4 + 3][row] = va.w;
    }

    float mrow[4], invl[4];
#pragma unroll
    for (int ii = 0; ii < 4; ii++) {
        size_t ridx = bh * Sc + r0 + ty * 4 + ii;
        mrow[ii] = g_mbuf[ridx];
        invl[ii] = 1.0f / g_lbuf[ridx];
    }

    float cacc[4][4] = {};

    for (int jt = 0; jt <= it; jt++) {
        const int j0 = jt * 64;
        __syncthreads();
#pragma unroll
        for (int i = 0; i < 4; i++) {
            int id = tid + i * 256;
            int row = id >> 4;
            int c4 = (id & 15) << 2;
            float4 vk = *(const float4*)(kp + (size_t)(j0 + row) * Dc + c4);
            Kt[c4 + 0][row] = vk.x; Kt[c4 + 1][row] = vk.y;
            Kt[c4 + 2][row] = vk.z; Kt[c4 + 3][row] = vk.w;
            float4 vv = *(const float4*)(vp + (size_t)(j0 + row) * Dc + c4);
            *(float4*)&Vs[row][c4] = vv;
        }
        __syncthreads();

        float acc[4][4] = {};
#pragma unroll 8
        for (int kk = 0; kk < 64; kk++) {
            float4 qf = *(const float4*)&Qt[kk][ty * 4];
            float4 kf = *(const float4*)&Kt[kk][tx * 4];
            float qv[4] = {qf.x, qf.y, qf.z, qf.w};
            float kv[4] = {kf.x, kf.y, kf.z, kf.w};
#pragma unroll
            for (int ii = 0; ii < 4; ii++)
#pragma unroll
                for (int jj = 0; jj < 4; jj++)
                    acc[ii][jj] = fmaf(qv[ii], kv[jj], acc[ii][jj]);
        }

        const bool diag = (jt == it);
        float p[4][4];
#pragma unroll
        for (int ii = 0; ii < 4; ii++)
#pragma unroll
            for (int jj = 0; jj < 4; jj++) {
                float val;
                if (diag && (tx * 4 + jj) > (ty * 4 + ii)) {
                    val = 0.0f;
                } else {
                    val = __expf(acc[ii][jj] * 0.125f - mrow[ii]) * invl[ii];
                }
                p[ii][jj] = val;
            }

#pragma unroll
        for (int ii = 0; ii < 4; ii++) {
            int gi = r0 + ty * 4 + ii;
            float4 pr = make_float4(p[ii][0], p[ii][1], p[ii][2], p[ii][3]);
            *(float4*)&attnp[(size_t)gi * Sc + j0 + tx * 4] = pr;
            *(float4*)&Ps[ty * 4 + ii][tx * 4] = pr;
        }
        __syncthreads();

#pragma unroll 4
        for (int jj = 0; jj < 64; jj++) {
            float4 vf = *(const float4*)&Vs[jj][tx * 4];
#pragma unroll
            for (int ii = 0; ii < 4; ii++) {
                float pf = Ps[ty * 4 + ii][jj];
                cacc[ii][0] = fmaf(pf, vf.x, cacc[ii][0]);
                cacc[ii][1] = fmaf(pf, vf.y, cacc[ii][1]);
                cacc[ii][2] = fmaf(pf, vf.z, cacc[ii][2]);
                cacc[ii][3] = fmaf(pf, vf.w, cacc[ii][3]);
            }
        }
    }

    const int zc0 = (it + 1) * 64;
    for (int r = 0; r < 64; r++) {
        size_t rowoff = (size_t)(r0 + r) * Sc;
        for (int c = zc0 + tid * 4; c < Sc; c += 1024)
            *(float4*)&attnp[rowoff + c] = make_float4(0.f, 0.f, 0.f, 0.f);
    }

#pragma unroll
    for (int ii = 0; ii < 4; ii++) {
        int gi = r0 + ty * 4 + ii;
        *(float4*)&g_ctx[((size_t)b * Sc + gi) * Dc + h * DPc + tx * 4] =
            make_float4(cacc[ii][0], cacc[ii][1], cacc[ii][2], cacc[ii][3]);
    }
}

// ---------------------------------------------------------------------------
extern "C" void kernel_launch(void* const* d_in, const int* in_sizes, int n_in,
                              void* d_out, int out_size)
{
    (void)in_sizes; (void)n_in; (void)out_size;
    const float* Q   = (const float*)d_in[0];
    const float* Kin = (const float*)d_in[1];
    const float* Vin = (const float*)d_in[2];
    const float* Wq = (const float*)d_in[4];
    const float* bq = (const float*)d_in[5];
    const float* Wk = (const float*)d_in[6];
    const float* bk = (const float*)d_in[7];
    const float* Wv = (const float*)d_in[8];
    const float* bv = (const float*)d_in[9];
    const float* Wo = (const float*)d_in[10];
    const float* bo = (const float*)d_in[11];

    float* out  = (float*)d_out;
    float* attn = out + SZ_QKV;
    float* qo   = attn + SZ_ATTN;
    float* ko   = qo + SZ_QKV;
    float* vo   = ko + SZ_QKV;

    void* ctxp = nullptr;
    cudaGetSymbolAddress(&ctxp, g_ctx);

    const int gsm = 8 * PLANE;   // 81920 B
    cudaFuncSetAttribute(gemm_mma_kernel,
                         cudaFuncAttributeMaxDynamicSharedMemorySize, gsm);
    const int pv_smem = 4 * 64 * 68 * (int)sizeof(float);
    cudaFuncSetAttribute(attn_pv_kernel,
                         cudaFuncAttributeMaxDynamicSharedMemorySize, pv_smem);

    const int M = Bc * Sc;
    dim3 ggrid(Dc / 128, M / 128);   // (8, 32)

    gemm_mma_kernel<<<ggrid, 256, gsm>>>(Q,   Wq, bq, qo, M, Dc, Dc);
    gemm_mma_kernel<<<ggrid, 256, gsm>>>(Kin, Wk, bk, ko, M, Dc, Dc);
    gemm_mma_kernel<<<ggrid, 256, gsm>>>(Vin, Wv, bv, vo, M, Dc, Dc);

    dim3 agrid(Sc / 64, Hc, Bc);
    attn_stats_kernel<<<agrid, 256>>>(qo, ko);
    attn_pv_kernel<<<agrid, 256, pv_smem>>>(qo, ko, vo, attn);

    gemm_mma_kernel<<<ggrid, 256, gsm>>>((const float*)ctxp, Wo, bo, out,
                                         M, Dc, Dc);
}

// round 4
// speedup vs baseline: 1.9398x; 1.4995x over previous
#include <cuda_runtime.h>
#include <cuda_bf16.h>
#include <math.h>
#include <stdint.h>

#define Bc 2
#define Sc 2048
#define Dc 1024
#define Hc 16
#define DPc 64

static const size_t SZ_QKV  = (size_t)Bc * Sc * Dc;        // 4194304
static const size_t SZ_ATTN = (size_t)Bc * Hc * Sc * Sc;   // 134217728

__device__ float g_ctx[(size_t)Bc * Sc * Dc];
__device__ float g_mbuf[(size_t)Bc * Hc * Sc];
__device__ float g_lbuf[(size_t)Bc * Hc * Sc];

// ---------------------------------------------------------------------------
// helpers
// ---------------------------------------------------------------------------
__device__ __forceinline__ uint32_t smem_u32(const void* p) {
    uint32_t a;
    asm("{ .reg .u64 t; cvta.to.shared.u64 t, %1; cvt.u32.u64 %0, t; }"
        : "=r"(a) : "l"(p));
    return a;
}
__device__ __forceinline__ void mma16816(float* d, const uint32_t* a, const uint32_t* b) {
    asm volatile(
        "mma.sync.aligned.m16n8k16.row.col.f32.bf16.bf16.f32 "
        "{%0,%1,%2,%3}, {%4,%5,%6,%7}, {%8,%9}, {%0,%1,%2,%3};"
        : "+f"(d[0]), "+f"(d[1]), "+f"(d[2]), "+f"(d[3])
        : "r"(a[0]), "r"(a[1]), "r"(a[2]), "r"(a[3]), "r"(b[0]), "r"(b[1]));
}
__device__ __forceinline__ void ldsm4(uint32_t* r, uint32_t addr) {
    asm volatile("ldmatrix.sync.aligned.m8n8.x4.shared.b16 {%0,%1,%2,%3}, [%4];"
                 : "=r"(r[0]), "=r"(r[1]), "=r"(r[2]), "=r"(r[3]) : "r"(addr));
}
__device__ __forceinline__ uint32_t pack_hi(float x, float y) {
    __nv_bfloat162 h = __float22bfloat162_rn(make_float2(x, y));
    return *(uint32_t*)&h;
}
__device__ __forceinline__ uint32_t pack_lo(float x, float y) {
    __nv_bfloat16 hx = __float2bfloat16(x), hy = __float2bfloat16(y);
    __nv_bfloat162 l = __float22bfloat162_rn(
        make_float2(x - __bfloat162float(hx), y - __bfloat162float(hy)));
    return *(uint32_t*)&l;
}

// ---------------------------------------------------------------------------
// Tensor-core GEMM (unchanged from R3): C = A @ B^T + bias, bf16 hi/lo split
// ---------------------------------------------------------------------------
#define ROWB 40
#define PLANE (128 * ROWB * 2)

__global__ __launch_bounds__(256, 1)
void gemm_mma_kernel(const float* __restrict__ A, const float* __restrict__ B,
                     const float* __restrict__ bias, float* __restrict__ C,
                     int M, int N, int K)
{
    extern __shared__ __align__(128) char sm[];
    const uint32_t smb = smem_u32(sm);
    const int tid = threadIdx.x;
    const int wid = tid >> 5, lane = tid & 31;
    const int m0 = blockIdx.y * 128, n0 = blockIdx.x * 128;
    const int warp_m = (wid & 1) * 64;
    const int warp_n = (wid >> 1) * 32;

    auto plane = [&](int buf, int p) -> uint32_t { return (uint32_t)((buf * 4 + p) * PLANE); };

    float acc[4][4][4];
#pragma unroll
    for (int i = 0; i < 4; i++)
#pragma unroll
        for (int j = 0; j < 4; j++)
#pragma unroll
            for (int c = 0; c < 4; c++) acc[i][j][c] = 0.0f;

    const int nch = K / 32;
    float4 ra[4], rb[4];

    auto load_regs = [&](int ch) {
        const size_t gk = (size_t)ch * 32;
#pragma unroll
        for (int e = 0; e < 4; e++) {
            int id = tid + e * 256;
            int row = id >> 3;
            int c4 = (id & 7) << 2;
            ra[e] = *(const float4*)(A + (size_t)(m0 + row) * K + gk + c4);
            rb[e] = *(const float4*)(B + (size_t)(n0 + row) * K + gk + c4);
        }
    };
    auto sts_regs = [&](int buf) {
#pragma unroll
        for (int e = 0; e < 4; e++) {
            int id = tid + e * 256;
            int row = id >> 3;
            int c4 = (id & 7) << 2;
            uint32_t off = (uint32_t)(row * 80 + c4 * 2);
            uint2 h, l;
            h.x = pack_hi(ra[e].x, ra[e].y); h.y = pack_hi(ra[e].z, ra[e].w);
            l.x = pack_lo(ra[e].x, ra[e].y); l.y = pack_lo(ra[e].z, ra[e].w);
            *(uint2*)(sm + plane(buf, 0) + off) = h;
            *(uint2*)(sm + plane(buf, 1) + off) = l;
            h.x = pack_hi(rb[e].x, rb[e].y); h.y = pack_hi(rb[e].z, rb[e].w);
            l.x = pack_lo(rb[e].x, rb[e].y); l.y = pack_lo(rb[e].z, rb[e].w);
            *(uint2*)(sm + plane(buf, 2) + off) = h;
            *(uint2*)(sm + plane(buf, 3) + off) = l;
        }
    };

    load_regs(0);
    sts_regs(0);
    __syncthreads();

    for (int ch = 0; ch < nch; ch++) {
        const int buf = ch & 1;
        if (ch + 1 < nch) load_regs(ch + 1);

        const int arow = lane & 15;
        const int acol = (lane >> 4) * 8;
        const int bg = lane >> 3, bw = lane & 7;

#pragma unroll
        for (int ks = 0; ks < 2; ks++) {
            const int k16 = ks * 16;
            uint32_t ah[4][4], al[4][4];
#pragma unroll
            for (int mt = 0; mt < 4; mt++) {
                uint32_t off = (uint32_t)((warp_m + mt * 16 + arow) * 80 + (k16 + acol) * 2);
                ldsm4(ah[mt], smb + plane(buf, 0) + off);
                ldsm4(al[mt], smb + plane(buf, 1) + off);
            }
            uint32_t bh[4][2], bl[4][2];
#pragma unroll
            for (int nb = 0; nb < 2; nb++) {
                uint32_t off = (uint32_t)((warp_n + nb * 16 + (bg & 1) * 8 + bw) * 80
                                          + (k16 + (bg >> 1) * 8) * 2);
                uint32_t t[4];
                ldsm4(t, smb + plane(buf, 2) + off);
                bh[nb * 2 + 0][0] = t[0]; bh[nb * 2 + 0][1] = t[2];
                bh[nb * 2 + 1][0] = t[1]; bh[nb * 2 + 1][1] = t[3];
                ldsm4(t, smb + plane(buf, 3) + off);
                bl[nb * 2 + 0][0] = t[0]; bl[nb * 2 + 0][1] = t[2];
                bl[nb * 2 + 1][0] = t[1]; bl[nb * 2 + 1][1] = t[3];
            }
#pragma unroll
            for (int mt = 0; mt < 4; mt++)
#pragma unroll
                for (int nt = 0; nt < 4; nt++) {
                    mma16816(acc[mt][nt], ah[mt], bh[nt]);
                    mma16816(acc[mt][nt], ah[mt], bl[nt]);
                    mma16816(acc[mt][nt], al[mt], bh[nt]);
                }
        }

        if (ch + 1 < nch) sts_regs((ch + 1) & 1);
        __syncthreads();
    }

    const int lr = lane >> 2, lc = (lane & 3) * 2;
#pragma unroll
    for (int nt = 0; nt < 4; nt++) {
        int col = n0 + warp_n + nt * 8 + lc;
        float2 bv = *(const float2*)&bias[col];
#pragma unroll
        for (int mt = 0; mt < 4; mt++) {
            int r0 = m0 + warp_m + mt * 16 + lr;
            float2 o0 = make_float2(acc[mt][nt][0] + bv.x, acc[mt][nt][1] + bv.y);
            float2 o1 = make_float2(acc[mt][nt][2] + bv.x, acc[mt][nt][3] + bv.y);
            *(float2*)(C + (size_t)r0 * N + col) = o0;
            *(float2*)(C + (size_t)(r0 + 8) * N + col) = o1;
        }
    }
}

// ---------------------------------------------------------------------------
// MMA-based attention. 128x128 S tile per CTA, 8 warps (warp tile 64x32).
// Smem rows: Q/K tiles 72 bf16 (144B, ldmatrix conflict-free),
// V^T / P tiles 136 bf16 (272B).
// ---------------------------------------------------------------------------
#define QROWB 144
#define VROWB 272
#define AQH 0
#define AQL 18432
#define AKH 36864
#define AKL 55296
// pass1 extras
#define ASRM 73728
#define ASRL 75776
#define SM1_TOT 77824
// pass2 extras
#define AVH 73728
#define AVL 91136
#define APH 108544
#define APL 143360
#define SM2_TOT 178176

// load a 128x64 fp32 tile (row stride ldg) into hi/lo bf16 smem planes
__device__ __forceinline__ void load_tile_hilo(const float* gp, char* sm,
                                               uint32_t offH, uint32_t offL, int tid)
{
#pragma unroll
    for (int e = 0; e < 8; e++) {
        int id = tid + e * 256;          // 0..2047
        int row = id >> 4;               // 0..127
        int c = (id & 15) << 2;          // 0..60
        float4 v = *(const float4*)(gp + (size_t)row * Dc + c);
        uint32_t off = (uint32_t)(row * QROWB + c * 2);
        uint2 h, l;
        h.x = pack_hi(v.x, v.y); h.y = pack_hi(v.z, v.w);
        l.x = pack_lo(v.x, v.y); l.y = pack_lo(v.z, v.w);
        *(uint2*)(sm + offH + off) = h;
        *(uint2*)(sm + offL + off) = l;
    }
}

// compute S tile fragments: acc[mt][nt][4] += (Qhi+Qlo)(Khi+Klo)^T (3 terms)
__device__ __forceinline__ void s_tile_mma(float acc[4][4][4], uint32_t smb,
                                           int warp_m, int warp_n, int lane)
{
    const int arow = lane & 15;
    const int acol = (lane >> 4) * 8;
    const int bg = lane >> 3, bw = lane & 7;
#pragma unroll
    for (int ks = 0; ks < 4; ks++) {
        const int k16 = ks * 16;
        uint32_t ah[4][4], al[4][4];
#pragma unroll
        for (int mt = 0; mt < 4; mt++) {
            uint32_t off = (uint32_t)((warp_m + mt * 16 + arow) * QROWB + (k16 + acol) * 2);
            ldsm4(ah[mt], smb + AQH + off);
            ldsm4(al[mt], smb + AQL + off);
        }
        uint32_t bh[4][2], bl[4][2];
#pragma unroll
        for (int nb = 0; nb < 2; nb++) {
            uint32_t off = (uint32_t)((warp_n + nb * 16 + (bg & 1) * 8 + bw) * QROWB
                                      + (k16 + (bg >> 1) * 8) * 2);
            uint32_t t[4];
            ldsm4(t, smb + AKH + off);
            bh[nb * 2 + 0][0] = t[0]; bh[nb * 2 + 0][1] = t[2];
            bh[nb * 2 + 1][0] = t[1]; bh[nb * 2 + 1][1] = t[3];
            ldsm4(t, smb + AKL + off);
            bl[nb * 2 + 0][0] = t[0]; bl[nb * 2 + 0][1] = t[2];
            bl[nb * 2 + 1][0] = t[1]; bl[nb * 2 + 1][1] = t[3];
        }
#pragma unroll
        for (int mt = 0; mt < 4; mt++)
#pragma unroll
            for (int nt = 0; nt < 4; nt++) {
                mma16816(acc[mt][nt], ah[mt], bh[nt]);
                mma16816(acc[mt][nt], ah[mt], bl[nt]);
                mma16816(acc[mt][nt], al[mt], bh[nt]);
            }
    }
}

// ---------------------------------------------------------------------------
// Pass 1: row max + sum-exp stats via mma
// ---------------------------------------------------------------------------
__global__ __launch_bounds__(256, 1)
void attn_stats_mma(const float* __restrict__ q, const float* __restrict__ k)
{
    extern __shared__ __align__(128) char sm[];
    const uint32_t smb = smem_u32(sm);
    const int tid = threadIdx.x;
    const int wid = tid >> 5, lane = tid & 31;
    const int b = blockIdx.z, h = blockIdx.y, it = blockIdx.x;
    const int r0 = it * 128;
    const int warp_m = (wid & 1) * 64;
    const int warp_n = (wid >> 1) * 32;
    const int lr = lane >> 2, lc2 = (lane & 3) * 2;

    const float* qp = q + ((size_t)b * Sc + r0) * Dc + h * DPc;
    const float* kp = k + (size_t)b * Sc * Dc + h * DPc;

    load_tile_hilo(qp, sm, AQH, AQL, tid);

    float tm[4][2], tl[4][2];
#pragma unroll
    for (int mt = 0; mt < 4; mt++)
#pragma unroll
        for (int hf = 0; hf < 2; hf++) { tm[mt][hf] = -1e30f; tl[mt][hf] = 0.0f; }

    for (int jt = 0; jt <= it; jt++) {
        const int j0 = jt * 128;
        __syncthreads();
        load_tile_hilo(kp + (size_t)j0 * Dc, sm, AKH, AKL, tid);
        __syncthreads();

        float acc[4][4][4];
#pragma unroll
        for (int i = 0; i < 4; i++)
#pragma unroll
            for (int j = 0; j < 4; j++)
#pragma unroll
                for (int c = 0; c < 4; c++) acc[i][j][c] = 0.0f;

        s_tile_mma(acc, smb, warp_m, warp_n, lane);

        const bool diag = (jt == it);
#pragma unroll
        for (int mt = 0; mt < 4; mt++)
#pragma unroll
            for (int hf = 0; hf < 2; hf++) {
                const int rowg = r0 + warp_m + mt * 16 + lr + hf * 8;
                float v[8];
#pragma unroll
                for (int nt = 0; nt < 4; nt++) {
                    int col = j0 + warp_n + nt * 8 + lc2;
                    float v0 = acc[mt][nt][hf * 2 + 0] * 0.125f;
                    float v1 = acc[mt][nt][hf * 2 + 1] * 0.125f;
                    if (diag && (col + 0) > rowg) v0 = -1e30f;
                    if (diag && (col + 1) > rowg) v1 = -1e30f;
                    v[nt * 2 + 0] = v0; v[nt * 2 + 1] = v1;
                }
                float mx = v[0];
#pragma unroll
                for (int e = 1; e < 8; e++) mx = fmaxf(mx, v[e]);
                float nm = fmaxf(tm[mt][hf], mx);
                float s = 0.0f;
#pragma unroll
                for (int e = 0; e < 8; e++) s += __expf(v[e] - nm);
                tl[mt][hf] = tl[mt][hf] * __expf(tm[mt][hf] - nm) + s;
                tm[mt][hf] = nm;
            }
    }

    // reduce across the 4 lanes sharing a row
#pragma unroll
    for (int off = 1; off <= 2; off <<= 1) {
#pragma unroll
        for (int mt = 0; mt < 4; mt++)
#pragma unroll
            for (int hf = 0; hf < 2; hf++) {
                float om = __shfl_xor_sync(0xffffffffu, tm[mt][hf], off);
                float ol = __shfl_xor_sync(0xffffffffu, tl[mt][hf], off);
                float nm = fmaxf(tm[mt][hf], om);
                tl[mt][hf] = tl[mt][hf] * __expf(tm[mt][hf] - nm) + ol * __expf(om - nm);
                tm[mt][hf] = nm;
            }
    }

    float* smRm = (float*)(sm + ASRM);   // [4][128]
    float* smRl = (float*)(sm + ASRL);
    if ((lane & 3) == 0) {
        const int g = wid >> 1;
#pragma unroll
        for (int mt = 0; mt < 4; mt++)
#pragma unroll
            for (int hf = 0; hf < 2; hf++) {
                int row = warp_m + mt * 16 + lr + hf * 8;
                smRm[g * 128 + row] = tm[mt][hf];
                smRl[g * 128 + row] = tl[mt][hf];
            }
    }
    __syncthreads();

    if (tid < 128) {
        float m0 = smRm[tid], m1 = smRm[128 + tid], m2 = smRm[256 + tid], m3 = smRm[384 + tid];
        float mx = fmaxf(fmaxf(m0, m1), fmaxf(m2, m3));
        float l = smRl[tid] * __expf(m0 - mx) + smRl[128 + tid] * __expf(m1 - mx)
                + smRl[256 + tid] * __expf(m2 - mx) + smRl[384 + tid] * __expf(m3 - mx);
        size_t ridx = ((size_t)(b * Hc + h)) * Sc + r0 + tid;
        g_mbuf[ridx] = mx;
        g_lbuf[ridx] = l;
    }
}

// ---------------------------------------------------------------------------
// Pass 2: recompute S via mma, write normalized attn, P@V via mma -> g_ctx
// ---------------------------------------------------------------------------
__global__ __launch_bounds__(256, 1)
void attn_pv_mma(const float* __restrict__ q, const float* __restrict__ k,
                 const float* __restrict__ v, float* __restrict__ attn)
{
    extern __shared__ __align__(128) char sm[];
    const uint32_t smb = smem_u32(sm);
    const int tid = threadIdx.x;
    const int wid = tid >> 5, lane = tid & 31;
    const int b = blockIdx.z, h = blockIdx.y, it = blockIdx.x;
    const int r0 = it * 128;
    const int warp_m = (wid & 1) * 64;
    const int warp_n = (wid >> 1) * 32;     // S-tile N split
    const int wnp = (wid >> 1) * 16;        // PV N (depth) split
    const int lr = lane >> 2, lc2 = (lane & 3) * 2;

    const float* qp = q + ((size_t)b * Sc + r0) * Dc + h * DPc;
    const float* kp = k + (size_t)b * Sc * Dc + h * DPc;
    const float* vp = v + (size_t)b * Sc * Dc + h * DPc;
    const size_t bh = (size_t)(b * Hc + h);
    float* attnp = attn + bh * Sc * Sc;

    load_tile_hilo(qp, sm, AQH, AQL, tid);

    float mrow[4][2], invl[4][2];
#pragma unroll
    for (int mt = 0; mt < 4; mt++)
#pragma unroll
        for (int hf = 0; hf < 2; hf++) {
            int row = warp_m + mt * 16 + lr + hf * 8;
            size_t ridx = bh * Sc + r0 + row;
            mrow[mt][hf] = g_mbuf[ridx];
            invl[mt][hf] = 1.0f / g_lbuf[ridx];
        }

    float ctx[4][2][4];
#pragma unroll
    for (int i = 0; i < 4; i++)
#pragma unroll
        for (int j = 0; j < 2; j++)
#pragma unroll
            for (int c = 0; c < 4; c++) ctx[i][j][c] = 0.0f;

    const int arow = lane & 15;
    const int acol = (lane >> 4) * 8;
    const int bg = lane >> 3, bw = lane & 7;

    for (int jt = 0; jt <= it; jt++) {
        const int j0 = jt * 128;
        __syncthreads();
        load_tile_hilo(kp + (size_t)j0 * Dc, sm, AKH, AKL, tid);
        // V tile transposed into Vt[d][j] hi/lo
        {
            const int j = tid >> 1;
            const int dbase = (tid & 1) * 32;
            const float* vr = vp + (size_t)(j0 + j) * Dc + dbase;
#pragma unroll
            for (int e = 0; e < 8; e++) {
                float4 vv = *(const float4*)(vr + e * 4);
                float vals[4] = {vv.x, vv.y, vv.z, vv.w};
#pragma unroll
                for (int q4 = 0; q4 < 4; q4++) {
                    int d = dbase + e * 4 + q4;
                    __nv_bfloat16 hb = __float2bfloat16(vals[q4]);
                    __nv_bfloat16 lb = __float2bfloat16(vals[q4] - __bfloat162float(hb));
                    *(__nv_bfloat16*)(sm + AVH + d * VROWB + j * 2) = hb;
                    *(__nv_bfloat16*)(sm + AVL + d * VROWB + j * 2) = lb;
                }
            }
        }
        __syncthreads();

        float acc[4][4][4];
#pragma unroll
        for (int i = 0; i < 4; i++)
#pragma unroll
            for (int j = 0; j < 4; j++)
#pragma unroll
                for (int c = 0; c < 4; c++) acc[i][j][c] = 0.0f;

        s_tile_mma(acc, smb, warp_m, warp_n, lane);

        const bool diag = (jt == it);
#pragma unroll
        for (int mt = 0; mt < 4; mt++)
#pragma unroll
            for (int hf = 0; hf < 2; hf++) {
                const int rowg = warp_m + mt * 16 + lr + hf * 8;
                const int growg = r0 + rowg;
#pragma unroll
                for (int nt = 0; nt < 4; nt++) {
                    int col = warp_n + nt * 8 + lc2;
                    float p0 = acc[mt][nt][hf * 2 + 0] * 0.125f;
                    float p1 = acc[mt][nt][hf * 2 + 1] * 0.125f;
                    p0 = (diag && (j0 + col + 0) > growg) ? 0.0f
                         : __expf(p0 - mrow[mt][hf]) * invl[mt][hf];
                    p1 = (diag && (j0 + col + 1) > growg) ? 0.0f
                         : __expf(p1 - mrow[mt][hf]) * invl[mt][hf];
                    *(float2*)&attnp[(size_t)growg * Sc + j0 + col] = make_float2(p0, p1);
                    *(uint32_t*)(sm + APH + rowg * VROWB + col * 2) = pack_hi(p0, p1);
                    *(uint32_t*)(sm + APL + rowg * VROWB + col * 2) = pack_lo(p0, p1);
                    // stash back for reuse? not needed
                    acc[mt][nt][hf * 2 + 0] = p0;
                    acc[mt][nt][hf * 2 + 1] = p1;
                }
            }
        __syncthreads();

        // PV: ctx += P[128x128] @ V[128x64]
#pragma unroll
        for (int ks = 0; ks < 8; ks++) {
            const int k16 = ks * 16;
            uint32_t ph[4][4], pl[4][4];
#pragma unroll
            for (int mt = 0; mt < 4; mt++) {
                uint32_t off = (uint32_t)((warp_m + mt * 16 + arow) * VROWB + (k16 + acol) * 2);
                ldsm4(ph[mt], smb + APH + off);
                ldsm4(pl[mt], smb + APL + off);
            }
            uint32_t vh[2][2], vl[2][2];
            {
                uint32_t off = (uint32_t)((wnp + (bg & 1) * 8 + bw) * VROWB
                                          + (k16 + (bg >> 1) * 8) * 2);
                uint32_t t[4];
                ldsm4(t, smb + AVH + off);
                vh[0][0] = t[0]; vh[0][1] = t[2];
                vh[1][0] = t[1]; vh[1][1] = t[3];
                ldsm4(t, smb + AVL + off);
                vl[0][0] = t[0]; vl[0][1] = t[2];
                vl[1][0] = t[1]; vl[1][1] = t[3];
            }
#pragma unroll
            for (int mt = 0; mt < 4; mt++)
#pragma unroll
                for (int ntp = 0; ntp < 2; ntp++) {
                    mma16816(ctx[mt][ntp], ph[mt], vh[ntp]);
                    mma16816(ctx[mt][ntp], ph[mt], vl[ntp]);
                    mma16816(ctx[mt][ntp], pl[mt], vh[ntp]);
                }
        }
    }

    // zero-fill causal upper triangle
    const int zc0 = (it + 1) * 128;
    for (int r = 0; r < 128; r++) {
        size_t rowoff = (size_t)(r0 + r) * Sc;
        for (int c = zc0 + tid * 4; c < Sc; c += 1024)
            *(float4*)&attnp[rowoff + c] = make_float4(0.f, 0.f, 0.f, 0.f);
    }

    // write ctx
#pragma unroll
    for (int mt = 0; mt < 4; mt++)
#pragma unroll
        for (int ntp = 0; ntp < 2; ntp++) {
            int dcol = h * DPc + wnp + ntp * 8 + lc2;
#pragma unroll
            for (int hf = 0; hf < 2; hf++) {
                int row = r0 + warp_m + mt * 16 + lr + hf * 8;
                *(float2*)&g_ctx[(size_t)((size_t)b * Sc + row) * Dc + dcol] =
                    make_float2(ctx[mt][ntp][hf * 2 + 0], ctx[mt][ntp][hf * 2 + 1]);
            }
        }
}

// ---------------------------------------------------------------------------
extern "C" void kernel_launch(void* const* d_in, const int* in_sizes, int n_in,
                              void* d_out, int out_size)
{
    (void)in_sizes; (void)n_in; (void)out_size;
    const float* Q   = (const float*)d_in[0];
    const float* Kin = (const float*)d_in[1];
    const float* Vin = (const float*)d_in[2];
    const float* Wq = (const float*)d_in[4];
    const float* bq = (const float*)d_in[5];
    const float* Wk = (const float*)d_in[6];
    const float* bk = (const float*)d_in[7];
    const float* Wv = (const float*)d_in[8];
    const float* bv = (const float*)d_in[9];
    const float* Wo = (const float*)d_in[10];
    const float* bo = (const float*)d_in[11];

    float* out  = (float*)d_out;
    float* attn = out + SZ_QKV;
    float* qo   = attn + SZ_ATTN;
    float* ko   = qo + SZ_QKV;
    float* vo   = ko + SZ_QKV;

    void* ctxp = nullptr;
    cudaGetSymbolAddress(&ctxp, g_ctx);

    const int gsm = 8 * PLANE;
    cudaFuncSetAttribute(gemm_mma_kernel,
                         cudaFuncAttributeMaxDynamicSharedMemorySize, gsm);
    cudaFuncSetAttribute(attn_stats_mma,
                         cudaFuncAttributeMaxDynamicSharedMemorySize, SM1_TOT);
    cudaFuncSetAttribute(attn_pv_mma,
                         cudaFuncAttributeMaxDynamicSharedMemorySize, SM2_TOT);

    const int M = Bc * Sc;
    dim3 ggrid(Dc / 128, M / 128);

    gemm_mma_kernel<<<ggrid, 256, gsm>>>(Q,   Wq, bq, qo, M, Dc, Dc);
    gemm_mma_kernel<<<ggrid, 256, gsm>>>(Kin, Wk, bk, ko, M, Dc, Dc);
    gemm_mma_kernel<<<ggrid, 256, gsm>>>(Vin, Wv, bv, vo, M, Dc, Dc);

    dim3 agrid(Sc / 128, Hc, Bc);
    attn_stats_mma<<<agrid, 256, SM1_TOT>>>(qo, ko);
    attn_pv_mma<<<agrid, 256, SM2_TOT>>>(qo, ko, vo, attn);

    gemm_mma_kernel<<<ggrid, 256, gsm>>>((const float*)ctxp, Wo, bo, out,
                                         M, Dc, Dc);
}